// round 15
// baseline (speedup 1.0000x reference)
#include <cuda_runtime.h>
#include <cuda_fp16.h>
#include <math.h>

#define NN 20000
#define EE 640000
#define HID 128
#define ASTR 136   // padded smem row stride in halfs (conflict-free ldmatrix)
#define CSR_NB 592 // persistent CSR kernel blocks (148 SMs x 4, co-resident)

// ---------------- scratch (device globals; no allocation) ----------------
__device__ int    g_is64;
__device__ int    g_bar[4];           // grid-barrier counters (rotating reset)
__device__ int    g_csrc[EE];
__device__ int    g_icnt[NN];
__device__ int    g_rowptr[NN + 1];
__device__ int    g_cursor[NN];
__device__ int    g_part[128];
__device__ float  g_dinv[NN];
__device__ __half g_x16 [NN * HID];   // feat@W_gcn (fp16)
__device__ __half g_h116[NN * HID];   // GCN out (fp16)
__device__ __half g_ns16[NN * HID];   // SAGE neighbor mean (fp16)

// ---------------- small helpers ----------------
__device__ __forceinline__ float gelu_f(float x) {
    return 0.5f * x * (1.0f + erff(x * 0.70710678118654752440f));
}
__device__ __forceinline__ float4 h4_to_f4(uint2 u) {
    __half2 a = *(__half2*)&u.x, b = *(__half2*)&u.y;
    float2 fa = __half22float2(a), fb = __half22float2(b);
    return make_float4(fa.x, fa.y, fb.x, fb.y);
}
__device__ __forceinline__ uint2 f4_to_h4(float4 f) {
    __half2 a = __floats2half2_rn(f.x, f.y), b = __floats2half2_rn(f.z, f.w);
    uint2 u;
    u.x = *(unsigned*)&a; u.y = *(unsigned*)&b;
    return u;
}
__device__ __forceinline__ unsigned smem_u32(const void* p) {
    return (unsigned)__cvta_generic_to_shared(p);
}
__device__ __forceinline__ void hmma16816(
    float& c0, float& c1, float& c2, float& c3,
    unsigned a0, unsigned a1, unsigned a2, unsigned a3,
    unsigned b0, unsigned b1)
{
    asm volatile(
        "mma.sync.aligned.m16n8k16.row.col.f32.f16.f16.f32 "
        "{%0,%1,%2,%3}, {%4,%5,%6,%7}, {%8,%9}, {%0,%1,%2,%3};"
        : "+f"(c0), "+f"(c1), "+f"(c2), "+f"(c3)
        : "r"(a0), "r"(a1), "r"(a2), "r"(a3), "r"(b0), "r"(b1));
}

// grid barrier (all CSR_NB blocks co-resident by construction)
__device__ __forceinline__ void gbar(int idx, int nb) {
    __syncthreads();
    if (threadIdx.x == 0) {
        __threadfence();
        atomicAdd(&g_bar[idx], 1);
        while (*((volatile int*)&g_bar[idx]) < nb) { }
        __threadfence();
    }
    __syncthreads();
}

// ---------------- persistent CSR build (one kernel, 4 grid barriers) ----------------
__global__ void __launch_bounds__(256) csr_build_k(
    const void* __restrict__ ei, int E, int n)
{
    const int tid = threadIdx.x, bid = blockIdx.x;
    const int nb = gridDim.x;
    const int gtid = bid * 256 + tid;
    const int gstride = nb * 256;

    // ---- P0: zero icnt; detect dtype; reset g_bar[3] (stale from prev replay)
    for (int i = gtid; i < n; i += gstride) g_icnt[i] = 0;
    if (bid == 0) {
        if (tid < 32) {
            const int* w = (const int*)ei;
            int h0 = w[2 * tid + 1];
            int h1 = w[2 * (tid + 32) + 1];
            unsigned b = __ballot_sync(0xFFFFFFFFu, (h0 | h1) != 0);
            if (tid == 0) g_is64 = (b == 0u) ? 1 : 0;
        }
        if (tid == 0) g_bar[3] = 0;
    }
    gbar(0, nb);

    // ---- P1: convert + count; keep edges in registers for the fill phase
    int es[5], ed[5];
    int ne = 0;
    const int is64 = g_is64;
    for (int e = gtid; e < E; e += gstride) {
        int s, d;
        if (is64) {
            const long long* p = (const long long*)ei;
            s = (int)p[e]; d = (int)p[E + e];
        } else {
            const int* p = (const int*)ei;
            s = p[e]; d = p[E + e];
        }
        es[ne] = s; ed[ne] = d; ne++;
        atomicAdd(&g_icnt[d], 1);
    }
    gbar(1, nb);
    if (bid == 0 && tid == 0) g_bar[0] = 0;   // safe: all blocks past B0

    // ---- P2: per-block scan partials (first SB blocks handle 256 nodes each)
    const int SB = (n + 255) / 256;
    int cdeg = 0, lexcl = 0;
    __shared__ int wsum[8];
    if (bid < SB) {
        int i = bid * 256 + tid;
        cdeg = (i < n) ? g_icnt[i] : 0;
        int lane = tid & 31, wid = tid >> 5;
        int incl = cdeg;
        #pragma unroll
        for (int off = 1; off < 32; off <<= 1) {
            int u = __shfl_up_sync(0xFFFFFFFFu, incl, off);
            if (lane >= off) incl += u;
        }
        if (lane == 31) wsum[wid] = incl;
        __syncthreads();
        if (wid == 0 && lane < 8) {
            int t = wsum[lane];
            #pragma unroll
            for (int off = 1; off < 8; off <<= 1) {
                int u = __shfl_up_sync(0xFFu, t, off);
                if (lane >= off) t += u;
            }
            wsum[lane] = t;
        }
        __syncthreads();
        int woff = (wid == 0) ? 0 : wsum[wid - 1];
        lexcl = woff + incl - cdeg;
        if (tid == 255) g_part[bid] = wsum[7];
    }
    gbar(2, nb);
    if (bid == 0 && tid == 0) g_bar[1] = 0;

    // ---- P3: cross-block offsets; write rowptr/cursor/dinv
    if (bid < SB) {
        __shared__ int s_off;
        if (tid == 0) {
            int o = 0;
            for (int b = 0; b < bid; b++) o += g_part[b];
            s_off = o;
            if (bid == SB - 1) g_rowptr[n] = o + g_part[bid];
        }
        __syncthreads();
        int i = bid * 256 + tid;
        if (i < n) {
            int run = s_off + lexcl;
            g_rowptr[i] = run;
            g_cursor[i] = run;
            g_dinv[i]   = rsqrtf((float)cdeg + 1.0f);
        }
    }
    gbar(3, nb);
    if (bid == 0 && tid == 0) g_bar[2] = 0;

    // ---- P4: fill from registers (no edge re-read)
    int k = 0;
    for (int e = gtid; e < E; e += gstride) {
        int slot = atomicAdd(&g_cursor[ed[k]], 1);
        g_csrc[slot] = es[k];
        k++;
    }
}

// ---------------- HMMA GEMM machinery (64-row tiles, 256 threads) ----------------
__device__ __forceinline__ void stage_A16f(const float* __restrict__ A,
                                           __half* As16, int row_base, int nrows) {
    int tid = threadIdx.x;
    #pragma unroll
    for (int i = tid; i < 64 * 32; i += 256) {
        int r = i >> 5, c4 = i & 31;
        float4 v = make_float4(0.f, 0.f, 0.f, 0.f);
        if (row_base + r < nrows)
            v = ((const float4*)A)[(size_t)(row_base + r) * 32 + c4];
        *(uint2*)(As16 + r * ASTR + c4 * 4) = f4_to_h4(v);
    }
}
__device__ __forceinline__ void stage_A16h(const __half* __restrict__ A,
                                           __half* As16, int row_base, int nrows) {
    int tid = threadIdx.x;
    #pragma unroll
    for (int i = tid; i < 64 * 32; i += 256) {
        int r = i >> 5, c4 = i & 31;
        uint2 v = make_uint2(0u, 0u);
        if (row_base + r < nrows)
            v = ((const uint2*)A)[(size_t)(row_base + r) * 32 + c4];
        *(uint2*)(As16 + r * ASTR + c4 * 4) = v;
    }
}
template<int BN>
__device__ __forceinline__ void stage_W16(const float* __restrict__ W, __half* Ws16) {
    int tid = threadIdx.x;
    #pragma unroll
    for (int i = tid; i < 128 * BN / 4; i += 256) {
        int k = i / (BN / 4), c4 = i % (BN / 4);
        float4 v = ((const float4*)W)[i];
        *(uint2*)(Ws16 + k * ASTR + c4 * 4) = f4_to_h4(v);
    }
}

template<int NT>
__device__ __forceinline__ void hmma_pass(const __half* As16, const __half* Ws16,
                                          int rl0, int nbase, float (&c)[8][4])
{
    const int lane = threadIdx.x & 31;
    const int t = lane >> 3, i = lane & 7;
    #pragma unroll
    for (int k0 = 0; k0 < 128; k0 += 16) {
        unsigned a0, a1, a2, a3;
        {
            int row = rl0 + (t & 1) * 8 + i;
            int col = k0 + (t >> 1) * 8;
            unsigned addr = smem_u32(As16 + row * ASTR + col);
            asm volatile("ldmatrix.sync.aligned.m8n8.x4.shared.b16 {%0,%1,%2,%3}, [%4];"
                : "=r"(a0), "=r"(a1), "=r"(a2), "=r"(a3) : "r"(addr));
        }
        unsigned b[2 * NT];
        #pragma unroll
        for (int m = 0; m < NT / 2; m++) {
            int krow = k0 + (t & 1) * 8 + i;
            int col = nbase + m * 16 + (t >> 1) * 8;
            unsigned addr = smem_u32(Ws16 + krow * ASTR + col);
            asm volatile("ldmatrix.sync.aligned.m8n8.x4.trans.shared.b16 {%0,%1,%2,%3}, [%4];"
                : "=r"(b[4*m]), "=r"(b[4*m+1]), "=r"(b[4*m+2]), "=r"(b[4*m+3]) : "r"(addr));
        }
        #pragma unroll
        for (int j = 0; j < NT; j++)
            hmma16816(c[j][0], c[j][1], c[j][2], c[j][3],
                      a0, a1, a2, a3, b[2*j], b[2*j+1]);
    }
}

// ---------------- GEMM1: g_x16 = fp16(feat @ W_gcn) ----------------
__global__ void __launch_bounds__(256) gemm1_k(
    const float* __restrict__ A, const float* __restrict__ W, int nrows)
{
    extern __shared__ __half sh[];
    __half* As16 = sh;
    __half* Ws16 = sh + 64 * ASTR;
    const int row_base = blockIdx.x * 64;
    const int tid = threadIdx.x, lane = tid & 31, wid = tid >> 5;
    const int rl0 = (wid & 3) * 16;
    const int nbase = (wid >> 2) * 64;

    stage_A16f(A, As16, row_base, nrows);
    stage_W16<128>(W, Ws16);
    __syncthreads();

    float c[8][4];
    #pragma unroll
    for (int j = 0; j < 8; j++)
        #pragma unroll
        for (int q = 0; q < 4; q++) c[j][q] = 0.f;
    hmma_pass<8>(As16, Ws16, rl0, nbase, c);

    int r0 = row_base + rl0 + lane / 4;
    #pragma unroll
    for (int j = 0; j < 8; j++) {
        int cb = nbase + j * 8 + 2 * (lane & 3);
        if (r0 < nrows)
            *(__half2*)&g_x16[(size_t)r0 * 128 + cb] = __floats2half2_rn(c[j][0], c[j][1]);
        if (r0 + 8 < nrows)
            *(__half2*)&g_x16[(size_t)(r0 + 8) * 128 + cb] = __floats2half2_rn(c[j][2], c[j][3]);
    }
}

// ---------------- mega-fused HMMA: SAGE GEMM + value head + 3-layer MLP ----------------
__global__ void __launch_bounds__(256) mlp_fused_k(
    const float* __restrict__ Wl, const float* __restrict__ Wr,
    const float* __restrict__ bl,
    const float* __restrict__ W1, const float* __restrict__ b1,
    const float* __restrict__ W2, const float* __restrict__ b2,
    const float* __restrict__ W3, const float* __restrict__ b3,
    const float* __restrict__ Wv, const float* __restrict__ bv,
    float* __restrict__ means_out, float* __restrict__ values_out, int nrows)
{
    extern __shared__ __half sh[];
    __half* As16 = sh;
    __half* Ws16 = sh + 64 * ASTR;
    const int row_base = blockIdx.x * 64;
    const int tid = threadIdx.x, lane = tid & 31, wid = tid >> 5;
    const int rl0 = (wid & 3) * 16;
    const int nbase = (wid >> 2) * 64;

    float c[8][4];
    #pragma unroll
    for (int j = 0; j < 8; j++)
        #pragma unroll
        for (int q = 0; q < 4; q++) c[j][q] = 0.f;

    // --- SAGE pass 1: ns @ Wl ---
    stage_A16h(g_ns16, As16, row_base, nrows);
    stage_W16<128>(Wl, Ws16);
    __syncthreads();
    hmma_pass<8>(As16, Ws16, rl0, nbase, c);
    __syncthreads();
    // --- SAGE pass 2: + h1 @ Wr ---
    stage_A16h(g_h116, As16, row_base, nrows);
    stage_W16<128>(Wr, Ws16);
    __syncthreads();
    hmma_pass<8>(As16, Ws16, rl0, nbase, c);
    __syncthreads();

    // --- epilogue: h2 = relu(c + bl) -> As16 (fp16) ---
    {
        int rr = rl0 + lane / 4;
        #pragma unroll
        for (int j = 0; j < 8; j++) {
            int cb = nbase + j * 8 + 2 * (lane & 3);
            float v0 = fmaxf(c[j][0] + bl[cb],     0.f);
            float v1 = fmaxf(c[j][1] + bl[cb + 1], 0.f);
            float v2 = fmaxf(c[j][2] + bl[cb],     0.f);
            float v3 = fmaxf(c[j][3] + bl[cb + 1], 0.f);
            *(__half2*)(As16 + rr * ASTR + cb)       = __floats2half2_rn(v0, v1);
            *(__half2*)(As16 + (rr + 8) * ASTR + cb) = __floats2half2_rn(v2, v3);
        }
    }
    __syncthreads();

    // --- value head: values = h2 @ Wv + bv ---
    {
        int row = tid >> 2;          // 0..63
        int sub = tid & 3;           // 0..3
        const __half* hr = As16 + row * ASTR + sub * 32;
        const float* wv = Wv + sub * 32;
        float p = 0.f;
        #pragma unroll
        for (int j = 0; j < 16; j++) {
            __half2 h = *(const __half2*)(hr + 2 * j);
            float2 f = __half22float2(h);
            p = fmaf(f.x, wv[2 * j], p);
            p = fmaf(f.y, wv[2 * j + 1], p);
        }
        p += __shfl_xor_sync(0xFFFFFFFFu, p, 1);
        p += __shfl_xor_sync(0xFFFFFFFFu, p, 2);
        int grow = row_base + row;
        if (sub == 0 && grow < nrows) values_out[grow] = p + bv[0];
    }

    // --- MLP layers 1 & 2: As16 = gelu(As16 @ W + b) ---
    #pragma unroll 1
    for (int layer = 0; layer < 2; layer++) {
        const float* Wp = layer ? W2 : W1;
        const float* bp = layer ? b2 : b1;
        stage_W16<128>(Wp, Ws16);
        __syncthreads();
        #pragma unroll
        for (int j = 0; j < 8; j++)
            #pragma unroll
            for (int q = 0; q < 4; q++) c[j][q] = 0.f;
        hmma_pass<8>(As16, Ws16, rl0, nbase, c);
        __syncthreads();
        int rr = rl0 + lane / 4;
        #pragma unroll
        for (int j = 0; j < 8; j++) {
            int cb = nbase + j * 8 + 2 * (lane & 3);
            float v0 = gelu_f(c[j][0] + bp[cb]);
            float v1 = gelu_f(c[j][1] + bp[cb + 1]);
            float v2 = gelu_f(c[j][2] + bp[cb]);
            float v3 = gelu_f(c[j][3] + bp[cb + 1]);
            *(__half2*)(As16 + rr * ASTR + cb)       = __floats2half2_rn(v0, v1);
            *(__half2*)(As16 + (rr + 8) * ASTR + cb) = __floats2half2_rn(v2, v3);
        }
        __syncthreads();
    }

    // --- MLP layer 3 (BN=64): means = As16 @ W3 + b3 ---
    stage_W16<64>(W3, Ws16);
    __syncthreads();
    {
        const int nb2 = (wid >> 2) * 32;
        #pragma unroll
        for (int j = 0; j < 4; j++)
            #pragma unroll
            for (int q = 0; q < 4; q++) c[j][q] = 0.f;
        hmma_pass<4>(As16, Ws16, rl0, nb2, c);
        int r0 = row_base + rl0 + lane / 4;
        #pragma unroll
        for (int j = 0; j < 4; j++) {
            int cb = nb2 + j * 8 + 2 * (lane & 3);
            float2 o0 = make_float2(c[j][0] + b3[cb], c[j][1] + b3[cb + 1]);
            float2 o1 = make_float2(c[j][2] + b3[cb], c[j][3] + b3[cb + 1]);
            if (r0 < nrows)
                *(float2*)&means_out[(size_t)r0 * 64 + cb] = o0;
            if (r0 + 8 < nrows)
                *(float2*)&means_out[(size_t)(r0 + 8) * 64 + cb] = o1;
        }
    }
}

// ---------------- GCN gather (fp16 payload/output, 4-edge unroll) ----------------
__global__ void gcn_gather_k(const float* __restrict__ bias, int n) {
    int node = blockIdx.x * (blockDim.x >> 5) + (threadIdx.x >> 5);
    if (node >= n) return;
    int lane = threadIdx.x & 31;
    int col0 = lane * 4;
    int beg = g_rowptr[node], end = g_rowptr[node + 1];
    float dd = g_dinv[node];

    float4 sv = h4_to_f4(*(const uint2*)&g_x16[(size_t)node * HID + col0]);
    float sl = dd * dd;
    float4 acc = make_float4(sv.x * sl, sv.y * sl, sv.z * sl, sv.w * sl);

    int e = beg;
    for (; e + 3 < end; e += 4) {
        int s0 = g_csrc[e],     s1 = g_csrc[e + 1];
        int s2 = g_csrc[e + 2], s3 = g_csrc[e + 3];
        uint2 u0 = *(const uint2*)&g_x16[(size_t)s0 * HID + col0];
        uint2 u1 = *(const uint2*)&g_x16[(size_t)s1 * HID + col0];
        uint2 u2 = *(const uint2*)&g_x16[(size_t)s2 * HID + col0];
        uint2 u3 = *(const uint2*)&g_x16[(size_t)s3 * HID + col0];
        float c0 = g_dinv[s0] * dd, c1 = g_dinv[s1] * dd;
        float c2 = g_dinv[s2] * dd, c3 = g_dinv[s3] * dd;
        float4 v0 = h4_to_f4(u0), v1 = h4_to_f4(u1);
        float4 v2 = h4_to_f4(u2), v3 = h4_to_f4(u3);
        acc.x = fmaf(v0.x, c0, acc.x); acc.y = fmaf(v0.y, c0, acc.y);
        acc.z = fmaf(v0.z, c0, acc.z); acc.w = fmaf(v0.w, c0, acc.w);
        acc.x = fmaf(v1.x, c1, acc.x); acc.y = fmaf(v1.y, c1, acc.y);
        acc.z = fmaf(v1.z, c1, acc.z); acc.w = fmaf(v1.w, c1, acc.w);
        acc.x = fmaf(v2.x, c2, acc.x); acc.y = fmaf(v2.y, c2, acc.y);
        acc.z = fmaf(v2.z, c2, acc.z); acc.w = fmaf(v2.w, c2, acc.w);
        acc.x = fmaf(v3.x, c3, acc.x); acc.y = fmaf(v3.y, c3, acc.y);
        acc.z = fmaf(v3.z, c3, acc.z); acc.w = fmaf(v3.w, c3, acc.w);
    }
    for (; e < end; e++) {
        int s0 = g_csrc[e];
        float c0 = g_dinv[s0] * dd;
        float4 v0 = h4_to_f4(*(const uint2*)&g_x16[(size_t)s0 * HID + col0]);
        acc.x = fmaf(v0.x, c0, acc.x); acc.y = fmaf(v0.y, c0, acc.y);
        acc.z = fmaf(v0.z, c0, acc.z); acc.w = fmaf(v0.w, c0, acc.w);
    }
    float4 b4 = *(const float4*)&bias[col0];
    float4 o;
    o.x = fmaxf(acc.x + b4.x, 0.0f);
    o.y = fmaxf(acc.y + b4.y, 0.0f);
    o.z = fmaxf(acc.z + b4.z, 0.0f);
    o.w = fmaxf(acc.w + b4.w, 0.0f);
    *(uint2*)&g_h116[(size_t)node * HID + col0] = f4_to_h4(o);
}

// ---------------- SAGE gather (fp16 payload/output, 4-edge unroll) ----------------
__global__ void sage_gather_k(int n) {
    int node = blockIdx.x * (blockDim.x >> 5) + (threadIdx.x >> 5);
    if (node >= n) return;
    int lane = threadIdx.x & 31;
    int col0 = lane * 4;
    int beg = g_rowptr[node], end = g_rowptr[node + 1];
    float4 acc = make_float4(0.f, 0.f, 0.f, 0.f);

    int e = beg;
    for (; e + 3 < end; e += 4) {
        int s0 = g_csrc[e],     s1 = g_csrc[e + 1];
        int s2 = g_csrc[e + 2], s3 = g_csrc[e + 3];
        uint2 u0 = *(const uint2*)&g_h116[(size_t)s0 * HID + col0];
        uint2 u1 = *(const uint2*)&g_h116[(size_t)s1 * HID + col0];
        uint2 u2 = *(const uint2*)&g_h116[(size_t)s2 * HID + col0];
        uint2 u3 = *(const uint2*)&g_h116[(size_t)s3 * HID + col0];
        float4 v0 = h4_to_f4(u0), v1 = h4_to_f4(u1);
        float4 v2 = h4_to_f4(u2), v3 = h4_to_f4(u3);
        acc.x += (v0.x + v1.x) + (v2.x + v3.x);
        acc.y += (v0.y + v1.y) + (v2.y + v3.y);
        acc.z += (v0.z + v1.z) + (v2.z + v3.z);
        acc.w += (v0.w + v1.w) + (v2.w + v3.w);
    }
    for (; e < end; e++) {
        int s0 = g_csrc[e];
        float4 v0 = h4_to_f4(*(const uint2*)&g_h116[(size_t)s0 * HID + col0]);
        acc.x += v0.x; acc.y += v0.y; acc.z += v0.z; acc.w += v0.w;
    }
    int deg = end - beg;
    float inv = 1.0f / (float)max(deg, 1);
    acc.x *= inv; acc.y *= inv; acc.z *= inv; acc.w *= inv;
    *(uint2*)&g_ns16[(size_t)node * HID + col0] = f4_to_h4(acc);
}

// ---------------- launch ----------------
extern "C" void kernel_launch(void* const* d_in, const int* in_sizes, int n_in,
                              void* d_out, int out_size)
{
    const float* feat     = (const float*)d_in[0];
    const void*  ei       = d_in[1];
    const float* W_gcn    = (const float*)d_in[2];
    const float* b_gcn    = (const float*)d_in[3];
    const float* W_sage_l = (const float*)d_in[4];
    const float* b_sage_l = (const float*)d_in[5];
    const float* W_sage_r = (const float*)d_in[6];
    const float* W1       = (const float*)d_in[7];
    const float* b1       = (const float*)d_in[8];
    const float* W2       = (const float*)d_in[9];
    const float* b2       = (const float*)d_in[10];
    const float* W3       = (const float*)d_in[11];
    const float* b3       = (const float*)d_in[12];
    const float* Wv       = (const float*)d_in[13];
    const float* bv       = (const float*)d_in[14];

    const int N = in_sizes[0] / HID;   // 20000
    const int E = in_sizes[1] / 2;     // 640000

    float* means_out  = (float*)d_out;            // [N, 64]
    float* values_out = (float*)d_out + (size_t)N * 64;

    const int TB = 256;
    const int nw_blocks   = (N * 32 + TB - 1) / TB;   // warp per node
    const int gemm_blocks = (N + 63) / 64;            // 313

    const int SMEM = (64 * ASTR + 128 * ASTR) * 2;    // 52224 B

    static int init_done = 0;
    static cudaStream_t s2;
    static cudaEvent_t ev_fork, ev_join;
    if (!init_done) {
        cudaFuncSetAttribute(gemm1_k,
            cudaFuncAttributeMaxDynamicSharedMemorySize, SMEM);
        cudaFuncSetAttribute(mlp_fused_k,
            cudaFuncAttributeMaxDynamicSharedMemorySize, SMEM);
        cudaStreamCreateWithFlags(&s2, cudaStreamNonBlocking);
        cudaEventCreateWithFlags(&ev_fork, cudaEventDisableTiming);
        cudaEventCreateWithFlags(&ev_join, cudaEventDisableTiming);
        init_done = 1;
    }

    // fork: persistent CSR build on s2, GEMM1 on main stream — independent
    cudaEventRecord(ev_fork, 0);
    cudaStreamWaitEvent(s2, ev_fork, 0);

    csr_build_k<<<CSR_NB, TB, 0, s2>>>(ei, E, N);
    cudaEventRecord(ev_join, s2);

    gemm1_k<<<gemm_blocks, TB, SMEM>>>(feat, W_gcn, N);

    // join: gathers need both CSR and g_x16
    cudaStreamWaitEvent(0, ev_join, 0);
    gcn_gather_k<<<nw_blocks, TB>>>(b_gcn, N);
    sage_gather_k<<<nw_blocks, TB>>>(N);
    mlp_fused_k<<<gemm_blocks, TB, SMEM>>>(W_sage_l, W_sage_r, b_sage_l,
                                           W1, b1, W2, b2, W3, b3,
                                           Wv, bv, means_out, values_out, N);
}

// round 16
// speedup vs baseline: 1.1247x; 1.1247x over previous
#include <cuda_runtime.h>
#include <cuda_fp16.h>
#include <math.h>

#define NN 20000
#define EE 640000
#define HID 128
#define ASTR 136   // padded smem row stride in halfs (conflict-free ldmatrix)

// ---------------- scratch (device globals; no allocation) ----------------
__device__ int    g_is64;
__device__ int    g_flag;
__device__ int    g_src[EE];
__device__ int    g_dst[EE];
__device__ int    g_csrc[EE];
__device__ int    g_icnt[NN];
__device__ int    g_rowptr[NN + 1];
__device__ int    g_cursor[NN];
__device__ int    g_part[64];
__device__ float  g_dinv[NN];
__device__ __half g_x16 [NN * HID];   // feat@W_gcn (fp16)
__device__ __half g_h116[NN * HID];   // GCN out (fp16)
__device__ __half g_ns16[NN * HID];   // SAGE neighbor mean (fp16)

// ---------------- small helpers ----------------
__device__ __forceinline__ float gelu_f(float x) {
    return 0.5f * x * (1.0f + erff(x * 0.70710678118654752440f));
}
__device__ __forceinline__ uint2 f4_to_h4(float4 f) {
    __half2 a = __floats2half2_rn(f.x, f.y), b = __floats2half2_rn(f.z, f.w);
    uint2 u;
    u.x = *(unsigned*)&a; u.y = *(unsigned*)&b;
    return u;
}
__device__ __forceinline__ unsigned smem_u32(const void* p) {
    return (unsigned)__cvta_generic_to_shared(p);
}
__device__ __forceinline__ void hmma16816(
    float& c0, float& c1, float& c2, float& c3,
    unsigned a0, unsigned a1, unsigned a2, unsigned a3,
    unsigned b0, unsigned b1)
{
    asm volatile(
        "mma.sync.aligned.m16n8k16.row.col.f32.f16.f16.f32 "
        "{%0,%1,%2,%3}, {%4,%5,%6,%7}, {%8,%9}, {%0,%1,%2,%3};"
        : "+f"(c0), "+f"(c1), "+f"(c2), "+f"(c3)
        : "r"(a0), "r"(a1), "r"(a2), "r"(a3), "r"(b0), "r"(b1));
}

// ---------------- init ----------------
__global__ void init_k(const int* __restrict__ ei_words, int n) {
    int idx = blockIdx.x * blockDim.x + threadIdx.x;
    int stride = gridDim.x * blockDim.x;
    for (int i = idx; i < n; i += stride) g_icnt[i] = 0;
    if (idx == 0) g_flag = 0;
    if (blockIdx.x == 0 && threadIdx.x < 64) {
        int hi = ei_words[2 * threadIdx.x + 1];
        __shared__ unsigned s[2];
        unsigned b = __ballot_sync(0xFFFFFFFFu, hi != 0);
        if ((threadIdx.x & 31) == 0) s[threadIdx.x >> 5] = b;
        __syncthreads();
        if (threadIdx.x == 0) g_is64 = ((s[0] | s[1]) == 0u) ? 1 : 0;
    }
}

__global__ void convert_count_k(const void* __restrict__ ei, int E) {
    int e = blockIdx.x * blockDim.x + threadIdx.x;
    if (e >= E) return;
    int s, d;
    if (g_is64) {
        const long long* p = (const long long*)ei;
        s = (int)p[e]; d = (int)p[E + e];
    } else {
        const int* p = (const int*)ei;
        s = p[e]; d = p[E + e];
    }
    g_src[e] = s;
    g_dst[e] = d;
    atomicAdd(&g_icnt[d], 1);
}

// ---------------- single-launch scan ----------------
__global__ void __launch_bounds__(1024) scan_fused_k(int n) {
    __shared__ int wsum[32];
    __shared__ int s_off;
    int tid = threadIdx.x, lane = tid & 31, wid = tid >> 5;
    int i = blockIdx.x * 1024 + tid;
    int c = (i < n) ? g_icnt[i] : 0;
    int incl = c;
    #pragma unroll
    for (int off = 1; off < 32; off <<= 1) {
        int u = __shfl_up_sync(0xFFFFFFFFu, incl, off);
        if (lane >= off) incl += u;
    }
    if (lane == 31) wsum[wid] = incl;
    __syncthreads();
    if (wid == 0) {
        int t = wsum[lane];
        #pragma unroll
        for (int off = 1; off < 32; off <<= 1) {
            int u = __shfl_up_sync(0xFFFFFFFFu, t, off);
            if (lane >= off) t += u;
        }
        wsum[lane] = t;
    }
    __syncthreads();
    int warp_off = (wid == 0) ? 0 : wsum[wid - 1];
    int local_excl = warp_off + incl - c;
    int block_total = wsum[31];

    if (tid == 0) {
        g_part[blockIdx.x] = block_total;
        __threadfence();
        atomicAdd(&g_flag, 1);
        while (atomicAdd(&g_flag, 0) < (int)gridDim.x) { }
        __threadfence();
        int o = 0;
        for (int b = 0; b < (int)blockIdx.x; b++) o += g_part[b];
        s_off = o;
        if (blockIdx.x == gridDim.x - 1) g_rowptr[n] = o + block_total;
    }
    __syncthreads();
    int run = s_off + local_excl;
    if (i < n) {
        g_rowptr[i] = run;
        g_cursor[i] = run;
        g_dinv[i]   = rsqrtf((float)c + 1.0f);
    }
}

__global__ void fill_k(int E) {
    int e = blockIdx.x * blockDim.x + threadIdx.x;
    if (e >= E) return;
    int d = g_dst[e];
    int slot = atomicAdd(&g_cursor[d], 1);
    g_csrc[slot] = g_src[e];
}

// ---------------- HMMA GEMM machinery (64-row tiles, 256 threads) ----------------
__device__ __forceinline__ void stage_A16f(const float* __restrict__ A,
                                           __half* As16, int row_base, int nrows) {
    int tid = threadIdx.x;
    #pragma unroll
    for (int i = tid; i < 64 * 32; i += 256) {
        int r = i >> 5, c4 = i & 31;
        float4 v = make_float4(0.f, 0.f, 0.f, 0.f);
        if (row_base + r < nrows)
            v = ((const float4*)A)[(size_t)(row_base + r) * 32 + c4];
        *(uint2*)(As16 + r * ASTR + c4 * 4) = f4_to_h4(v);
    }
}
__device__ __forceinline__ void stage_A16h(const __half* __restrict__ A,
                                           __half* As16, int row_base, int nrows) {
    int tid = threadIdx.x;
    #pragma unroll
    for (int i = tid; i < 64 * 32; i += 256) {
        int r = i >> 5, c4 = i & 31;
        uint2 v = make_uint2(0u, 0u);
        if (row_base + r < nrows)
            v = ((const uint2*)A)[(size_t)(row_base + r) * 32 + c4];
        *(uint2*)(As16 + r * ASTR + c4 * 4) = v;
    }
}
template<int BN>
__device__ __forceinline__ void stage_W16(const float* __restrict__ W, __half* Ws16) {
    int tid = threadIdx.x;
    #pragma unroll
    for (int i = tid; i < 128 * BN / 4; i += 256) {
        int k = i / (BN / 4), c4 = i % (BN / 4);
        float4 v = ((const float4*)W)[i];
        *(uint2*)(Ws16 + k * ASTR + c4 * 4) = f4_to_h4(v);
    }
}

template<int NT>
__device__ __forceinline__ void hmma_pass(const __half* As16, const __half* Ws16,
                                          int rl0, int nbase, float (&c)[8][4])
{
    const int lane = threadIdx.x & 31;
    const int t = lane >> 3, i = lane & 7;
    #pragma unroll
    for (int k0 = 0; k0 < 128; k0 += 16) {
        unsigned a0, a1, a2, a3;
        {
            int row = rl0 + (t & 1) * 8 + i;
            int col = k0 + (t >> 1) * 8;
            unsigned addr = smem_u32(As16 + row * ASTR + col);
            asm volatile("ldmatrix.sync.aligned.m8n8.x4.shared.b16 {%0,%1,%2,%3}, [%4];"
                : "=r"(a0), "=r"(a1), "=r"(a2), "=r"(a3) : "r"(addr));
        }
        unsigned b[2 * NT];
        #pragma unroll
        for (int m = 0; m < NT / 2; m++) {
            int krow = k0 + (t & 1) * 8 + i;
            int col = nbase + m * 16 + (t >> 1) * 8;
            unsigned addr = smem_u32(Ws16 + krow * ASTR + col);
            asm volatile("ldmatrix.sync.aligned.m8n8.x4.trans.shared.b16 {%0,%1,%2,%3}, [%4];"
                : "=r"(b[4*m]), "=r"(b[4*m+1]), "=r"(b[4*m+2]), "=r"(b[4*m+3]) : "r"(addr));
        }
        #pragma unroll
        for (int j = 0; j < NT; j++)
            hmma16816(c[j][0], c[j][1], c[j][2], c[j][3],
                      a0, a1, a2, a3, b[2*j], b[2*j+1]);
    }
}

// ---------------- GEMM1: g_x16 = fp16(feat @ W_gcn) ----------------
__global__ void __launch_bounds__(256) gemm1_k(
    const float* __restrict__ A, const float* __restrict__ W, int nrows)
{
    extern __shared__ __half sh[];
    __half* As16 = sh;
    __half* Ws16 = sh + 64 * ASTR;
    const int row_base = blockIdx.x * 64;
    const int tid = threadIdx.x, lane = tid & 31, wid = tid >> 5;
    const int rl0 = (wid & 3) * 16;
    const int nbase = (wid >> 2) * 64;

    stage_A16f(A, As16, row_base, nrows);
    stage_W16<128>(W, Ws16);
    __syncthreads();

    float c[8][4];
    #pragma unroll
    for (int j = 0; j < 8; j++)
        #pragma unroll
        for (int q = 0; q < 4; q++) c[j][q] = 0.f;
    hmma_pass<8>(As16, Ws16, rl0, nbase, c);

    int r0 = row_base + rl0 + lane / 4;
    #pragma unroll
    for (int j = 0; j < 8; j++) {
        int cb = nbase + j * 8 + 2 * (lane & 3);
        if (r0 < nrows)
            *(__half2*)&g_x16[(size_t)r0 * 128 + cb] = __floats2half2_rn(c[j][0], c[j][1]);
        if (r0 + 8 < nrows)
            *(__half2*)&g_x16[(size_t)(r0 + 8) * 128 + cb] = __floats2half2_rn(c[j][2], c[j][3]);
    }
}

// ---------------- mega-fused HMMA: SAGE GEMM + value head + 3-layer MLP ----------------
__global__ void __launch_bounds__(256) mlp_fused_k(
    const float* __restrict__ Wl, const float* __restrict__ Wr,
    const float* __restrict__ bl,
    const float* __restrict__ W1, const float* __restrict__ b1,
    const float* __restrict__ W2, const float* __restrict__ b2,
    const float* __restrict__ W3, const float* __restrict__ b3,
    const float* __restrict__ Wv, const float* __restrict__ bv,
    float* __restrict__ means_out, float* __restrict__ values_out, int nrows)
{
    extern __shared__ __half sh[];
    __half* As16 = sh;
    __half* Ws16 = sh + 64 * ASTR;
    const int row_base = blockIdx.x * 64;
    const int tid = threadIdx.x, lane = tid & 31, wid = tid >> 5;
    const int rl0 = (wid & 3) * 16;
    const int nbase = (wid >> 2) * 64;

    float c[8][4];
    #pragma unroll
    for (int j = 0; j < 8; j++)
        #pragma unroll
        for (int q = 0; q < 4; q++) c[j][q] = 0.f;

    // --- SAGE pass 1: ns @ Wl ---
    stage_A16h(g_ns16, As16, row_base, nrows);
    stage_W16<128>(Wl, Ws16);
    __syncthreads();
    hmma_pass<8>(As16, Ws16, rl0, nbase, c);
    __syncthreads();
    // --- SAGE pass 2: + h1 @ Wr ---
    stage_A16h(g_h116, As16, row_base, nrows);
    stage_W16<128>(Wr, Ws16);
    __syncthreads();
    hmma_pass<8>(As16, Ws16, rl0, nbase, c);
    __syncthreads();

    // --- epilogue: h2 = relu(c + bl) -> As16 (fp16) ---
    {
        int rr = rl0 + lane / 4;
        #pragma unroll
        for (int j = 0; j < 8; j++) {
            int cb = nbase + j * 8 + 2 * (lane & 3);
            float v0 = fmaxf(c[j][0] + bl[cb],     0.f);
            float v1 = fmaxf(c[j][1] + bl[cb + 1], 0.f);
            float v2 = fmaxf(c[j][2] + bl[cb],     0.f);
            float v3 = fmaxf(c[j][3] + bl[cb + 1], 0.f);
            *(__half2*)(As16 + rr * ASTR + cb)       = __floats2half2_rn(v0, v1);
            *(__half2*)(As16 + (rr + 8) * ASTR + cb) = __floats2half2_rn(v2, v3);
        }
    }
    __syncthreads();

    // --- value head: values = h2 @ Wv + bv ---
    {
        int row = tid >> 2;          // 0..63
        int sub = tid & 3;           // 0..3
        const __half* hr = As16 + row * ASTR + sub * 32;
        const float* wv = Wv + sub * 32;
        float p = 0.f;
        #pragma unroll
        for (int j = 0; j < 16; j++) {
            __half2 h = *(const __half2*)(hr + 2 * j);
            float2 f = __half22float2(h);
            p = fmaf(f.x, wv[2 * j], p);
            p = fmaf(f.y, wv[2 * j + 1], p);
        }
        p += __shfl_xor_sync(0xFFFFFFFFu, p, 1);
        p += __shfl_xor_sync(0xFFFFFFFFu, p, 2);
        int grow = row_base + row;
        if (sub == 0 && grow < nrows) values_out[grow] = p + bv[0];
    }

    // --- MLP layers 1 & 2: As16 = gelu(As16 @ W + b) ---
    #pragma unroll 1
    for (int layer = 0; layer < 2; layer++) {
        const float* Wp = layer ? W2 : W1;
        const float* bp = layer ? b2 : b1;
        stage_W16<128>(Wp, Ws16);
        __syncthreads();
        #pragma unroll
        for (int j = 0; j < 8; j++)
            #pragma unroll
            for (int q = 0; q < 4; q++) c[j][q] = 0.f;
        hmma_pass<8>(As16, Ws16, rl0, nbase, c);
        __syncthreads();
        int rr = rl0 + lane / 4;
        #pragma unroll
        for (int j = 0; j < 8; j++) {
            int cb = nbase + j * 8 + 2 * (lane & 3);
            float v0 = gelu_f(c[j][0] + bp[cb]);
            float v1 = gelu_f(c[j][1] + bp[cb + 1]);
            float v2 = gelu_f(c[j][2] + bp[cb]);
            float v3 = gelu_f(c[j][3] + bp[cb + 1]);
            *(__half2*)(As16 + rr * ASTR + cb)       = __floats2half2_rn(v0, v1);
            *(__half2*)(As16 + (rr + 8) * ASTR + cb) = __floats2half2_rn(v2, v3);
        }
        __syncthreads();
    }

    // --- MLP layer 3 (BN=64): means = As16 @ W3 + b3 ---
    stage_W16<64>(W3, Ws16);
    __syncthreads();
    {
        const int nb2 = (wid >> 2) * 32;
        #pragma unroll
        for (int j = 0; j < 4; j++)
            #pragma unroll
            for (int q = 0; q < 4; q++) c[j][q] = 0.f;
        hmma_pass<4>(As16, Ws16, rl0, nb2, c);
        int r0 = row_base + rl0 + lane / 4;
        #pragma unroll
        for (int j = 0; j < 4; j++) {
            int cb = nb2 + j * 8 + 2 * (lane & 3);
            float2 o0 = make_float2(c[j][0] + b3[cb], c[j][1] + b3[cb + 1]);
            float2 o1 = make_float2(c[j][2] + b3[cb], c[j][3] + b3[cb + 1]);
            if (r0 < nrows)
                *(float2*)&means_out[(size_t)r0 * 64 + cb] = o0;
            if (r0 + 8 < nrows)
                *(float2*)&means_out[(size_t)(r0 + 8) * 64 + cb] = o1;
        }
    }
}

// ---------------- GCN gather: 2 edges per warp iter (16 lanes x LDG.128) ----
__global__ void gcn_gather_k(const float* __restrict__ bias, int n) {
    int node = blockIdx.x * (blockDim.x >> 5) + (threadIdx.x >> 5);
    if (node >= n) return;
    int lane = threadIdx.x & 31;
    int half = lane >> 4;            // 0 or 1
    int col0 = (lane & 15) * 8;      // 8 halfs per lane
    int beg = g_rowptr[node], end = g_rowptr[node + 1];
    float dd = g_dinv[node];

    float acc[8];
    #pragma unroll
    for (int j = 0; j < 8; j++) acc[j] = 0.f;

    int e = beg + half;
    // unroll 2 (4 edges per warp iteration)
    for (; e + 2 < end; e += 4) {
        int s0 = g_csrc[e], s1 = g_csrc[e + 2];
        uint4 u0 = *(const uint4*)&g_x16[(size_t)s0 * HID + col0];
        uint4 u1 = *(const uint4*)&g_x16[(size_t)s1 * HID + col0];
        float c0 = g_dinv[s0] * dd, c1 = g_dinv[s1] * dd;
        __half2* h0 = (__half2*)&u0;
        __half2* h1 = (__half2*)&u1;
        #pragma unroll
        for (int j = 0; j < 4; j++) {
            float2 f0 = __half22float2(h0[j]);
            float2 f1 = __half22float2(h1[j]);
            acc[2*j]   = fmaf(f0.x, c0, acc[2*j]);
            acc[2*j+1] = fmaf(f0.y, c0, acc[2*j+1]);
            acc[2*j]   = fmaf(f1.x, c1, acc[2*j]);
            acc[2*j+1] = fmaf(f1.y, c1, acc[2*j+1]);
        }
    }
    for (; e < end; e += 2) {
        int s0 = g_csrc[e];
        uint4 u0 = *(const uint4*)&g_x16[(size_t)s0 * HID + col0];
        float c0 = g_dinv[s0] * dd;
        __half2* h0 = (__half2*)&u0;
        #pragma unroll
        for (int j = 0; j < 4; j++) {
            float2 f0 = __half22float2(h0[j]);
            acc[2*j]   = fmaf(f0.x, c0, acc[2*j]);
            acc[2*j+1] = fmaf(f0.y, c0, acc[2*j+1]);
        }
    }
    // combine halves
    #pragma unroll
    for (int j = 0; j < 8; j++)
        acc[j] += __shfl_xor_sync(0xFFFFFFFFu, acc[j], 16);

    if (half == 0) {
        // self-loop + bias + relu + store (lanes 0-15)
        uint4 su = *(const uint4*)&g_x16[(size_t)node * HID + col0];
        __half2* sh2 = (__half2*)&su;
        float sl = dd * dd;
        uint4 o;
        __half2* op = (__half2*)&o;
        #pragma unroll
        for (int j = 0; j < 4; j++) {
            float2 sf = __half22float2(sh2[j]);
            float v0 = acc[2*j]   + sf.x * sl + bias[col0 + 2*j];
            float v1 = acc[2*j+1] + sf.y * sl + bias[col0 + 2*j + 1];
            op[j] = __floats2half2_rn(fmaxf(v0, 0.f), fmaxf(v1, 0.f));
        }
        *(uint4*)&g_h116[(size_t)node * HID + col0] = o;
    }
}

// ---------------- SAGE gather: 2 edges per warp iter ----------------
__global__ void sage_gather_k(int n) {
    int node = blockIdx.x * (blockDim.x >> 5) + (threadIdx.x >> 5);
    if (node >= n) return;
    int lane = threadIdx.x & 31;
    int half = lane >> 4;
    int col0 = (lane & 15) * 8;
    int beg = g_rowptr[node], end = g_rowptr[node + 1];

    float acc[8];
    #pragma unroll
    for (int j = 0; j < 8; j++) acc[j] = 0.f;

    int e = beg + half;
    for (; e + 2 < end; e += 4) {
        int s0 = g_csrc[e], s1 = g_csrc[e + 2];
        uint4 u0 = *(const uint4*)&g_h116[(size_t)s0 * HID + col0];
        uint4 u1 = *(const uint4*)&g_h116[(size_t)s1 * HID + col0];
        __half2* h0 = (__half2*)&u0;
        __half2* h1 = (__half2*)&u1;
        #pragma unroll
        for (int j = 0; j < 4; j++) {
            float2 f0 = __half22float2(h0[j]);
            float2 f1 = __half22float2(h1[j]);
            acc[2*j]   += f0.x + f1.x;
            acc[2*j+1] += f0.y + f1.y;
        }
    }
    for (; e < end; e += 2) {
        int s0 = g_csrc[e];
        uint4 u0 = *(const uint4*)&g_h116[(size_t)s0 * HID + col0];
        __half2* h0 = (__half2*)&u0;
        #pragma unroll
        for (int j = 0; j < 4; j++) {
            float2 f0 = __half22float2(h0[j]);
            acc[2*j] += f0.x; acc[2*j+1] += f0.y;
        }
    }
    #pragma unroll
    for (int j = 0; j < 8; j++)
        acc[j] += __shfl_xor_sync(0xFFFFFFFFu, acc[j], 16);

    if (half == 0) {
        int deg = end - beg;
        float inv = 1.0f / (float)max(deg, 1);
        uint4 o;
        __half2* op = (__half2*)&o;
        #pragma unroll
        for (int j = 0; j < 4; j++)
            op[j] = __floats2half2_rn(acc[2*j] * inv, acc[2*j+1] * inv);
        *(uint4*)&g_ns16[(size_t)node * HID + col0] = o;
    }
}

// ---------------- launch ----------------
extern "C" void kernel_launch(void* const* d_in, const int* in_sizes, int n_in,
                              void* d_out, int out_size)
{
    const float* feat     = (const float*)d_in[0];
    const void*  ei       = d_in[1];
    const float* W_gcn    = (const float*)d_in[2];
    const float* b_gcn    = (const float*)d_in[3];
    const float* W_sage_l = (const float*)d_in[4];
    const float* b_sage_l = (const float*)d_in[5];
    const float* W_sage_r = (const float*)d_in[6];
    const float* W1       = (const float*)d_in[7];
    const float* b1       = (const float*)d_in[8];
    const float* W2       = (const float*)d_in[9];
    const float* b2       = (const float*)d_in[10];
    const float* W3       = (const float*)d_in[11];
    const float* b3       = (const float*)d_in[12];
    const float* Wv       = (const float*)d_in[13];
    const float* bv       = (const float*)d_in[14];

    const int N = in_sizes[0] / HID;   // 20000
    const int E = in_sizes[1] / 2;     // 640000

    float* means_out  = (float*)d_out;            // [N, 64]
    float* values_out = (float*)d_out + (size_t)N * 64;

    const int TB = 256;
    const int e_blocks    = (E + TB - 1) / TB;        // 2500
    const int nw_blocks   = (N * 32 + TB - 1) / TB;   // warp per node
    const int scan_blocks = (N + 1023) / 1024;        // 20
    const int gemm_blocks = (N + 63) / 64;            // 313

    const int SMEM = (64 * ASTR + 128 * ASTR) * 2;    // 52224 B

    static int init_done = 0;
    static cudaStream_t s2;
    static cudaEvent_t ev_fork, ev_join;
    if (!init_done) {
        cudaFuncSetAttribute(gemm1_k,
            cudaFuncAttributeMaxDynamicSharedMemorySize, SMEM);
        cudaFuncSetAttribute(mlp_fused_k,
            cudaFuncAttributeMaxDynamicSharedMemorySize, SMEM);
        cudaStreamCreateWithFlags(&s2, cudaStreamNonBlocking);
        cudaEventCreateWithFlags(&ev_fork, cudaEventDisableTiming);
        cudaEventCreateWithFlags(&ev_join, cudaEventDisableTiming);
        init_done = 1;
    }

    // fork: CSR build chain on s2, GEMM1 on main stream — independent
    cudaEventRecord(ev_fork, 0);
    cudaStreamWaitEvent(s2, ev_fork, 0);

    init_k<<<80, TB, 0, s2>>>((const int*)ei, N);
    convert_count_k<<<e_blocks, TB, 0, s2>>>(ei, E);
    scan_fused_k<<<scan_blocks, 1024, 0, s2>>>(N);
    fill_k<<<e_blocks, TB, 0, s2>>>(E);
    cudaEventRecord(ev_join, s2);

    gemm1_k<<<gemm_blocks, TB, SMEM>>>(feat, W_gcn, N);

    // join: gathers need both CSR and g_x16
    cudaStreamWaitEvent(0, ev_join, 0);
    gcn_gather_k<<<nw_blocks, TB>>>(b_gcn, N);
    sage_gather_k<<<nw_blocks, TB>>>(N);
    mlp_fused_k<<<gemm_blocks, TB, SMEM>>>(W_sage_l, W_sage_r, b_sage_l,
                                           W1, b1, W2, b2, W3, b3,
                                           Wv, bv, means_out, values_out, N);
}

// round 17
// speedup vs baseline: 1.1625x; 1.0336x over previous
#include <cuda_runtime.h>
#include <cuda_fp16.h>
#include <math.h>

#define NN 20000
#define EE 640000
#define HID 128
#define ASTR 136   // padded smem row stride in halfs (conflict-free ldmatrix)

// ---------------- scratch (device globals; no allocation) ----------------
__device__ int    g_is64;
__device__ int    g_flag;
__device__ int    g_src[EE];
__device__ int    g_dst[EE];
__device__ int    g_ord[EE];          // within-destination ordinal (from count)
__device__ int    g_csrc[EE];
__device__ int    g_icnt[NN];
__device__ int    g_rowptr[NN + 1];
__device__ int    g_part[64];
__device__ float  g_dinv[NN];
__device__ __half g_x16 [NN * HID];   // feat@W_gcn (fp16)
__device__ __half g_h116[NN * HID];   // GCN out (fp16)
__device__ __half g_ns16[NN * HID];   // SAGE neighbor mean (fp16)

// ---------------- small helpers ----------------
__device__ __forceinline__ float gelu_f(float x) {
    return 0.5f * x * (1.0f + erff(x * 0.70710678118654752440f));
}
__device__ __forceinline__ uint2 f4_to_h4(float4 f) {
    __half2 a = __floats2half2_rn(f.x, f.y), b = __floats2half2_rn(f.z, f.w);
    uint2 u;
    u.x = *(unsigned*)&a; u.y = *(unsigned*)&b;
    return u;
}
__device__ __forceinline__ unsigned smem_u32(const void* p) {
    return (unsigned)__cvta_generic_to_shared(p);
}
__device__ __forceinline__ void hmma16816(
    float& c0, float& c1, float& c2, float& c3,
    unsigned a0, unsigned a1, unsigned a2, unsigned a3,
    unsigned b0, unsigned b1)
{
    asm volatile(
        "mma.sync.aligned.m16n8k16.row.col.f32.f16.f16.f32 "
        "{%0,%1,%2,%3}, {%4,%5,%6,%7}, {%8,%9}, {%0,%1,%2,%3};"
        : "+f"(c0), "+f"(c1), "+f"(c2), "+f"(c3)
        : "r"(a0), "r"(a1), "r"(a2), "r"(a3), "r"(b0), "r"(b1));
}

// ---------------- init ----------------
__global__ void init_k(const int* __restrict__ ei_words, int n) {
    int idx = blockIdx.x * blockDim.x + threadIdx.x;
    int stride = gridDim.x * blockDim.x;
    for (int i = idx; i < n; i += stride) g_icnt[i] = 0;
    if (idx == 0) g_flag = 0;
    if (blockIdx.x == 0 && threadIdx.x < 64) {
        int hi = ei_words[2 * threadIdx.x + 1];
        __shared__ unsigned s[2];
        unsigned b = __ballot_sync(0xFFFFFFFFu, hi != 0);
        if ((threadIdx.x & 31) == 0) s[threadIdx.x >> 5] = b;
        __syncthreads();
        if (threadIdx.x == 0) g_is64 = ((s[0] | s[1]) == 0u) ? 1 : 0;
    }
}

// convert + count; atomic return value = within-dst ordinal (reused by fill)
__global__ void convert_count_k(const void* __restrict__ ei, int E) {
    int e = blockIdx.x * blockDim.x + threadIdx.x;
    if (e >= E) return;
    int s, d;
    if (g_is64) {
        const long long* p = (const long long*)ei;
        s = (int)p[e]; d = (int)p[E + e];
    } else {
        const int* p = (const int*)ei;
        s = p[e]; d = p[E + e];
    }
    g_src[e] = s;
    g_dst[e] = d;
    g_ord[e] = atomicAdd(&g_icnt[d], 1);
}

// ---------------- single-launch scan ----------------
__global__ void __launch_bounds__(1024) scan_fused_k(int n) {
    __shared__ int wsum[32];
    __shared__ int s_off;
    int tid = threadIdx.x, lane = tid & 31, wid = tid >> 5;
    int i = blockIdx.x * 1024 + tid;
    int c = (i < n) ? g_icnt[i] : 0;
    int incl = c;
    #pragma unroll
    for (int off = 1; off < 32; off <<= 1) {
        int u = __shfl_up_sync(0xFFFFFFFFu, incl, off);
        if (lane >= off) incl += u;
    }
    if (lane == 31) wsum[wid] = incl;
    __syncthreads();
    if (wid == 0) {
        int t = wsum[lane];
        #pragma unroll
        for (int off = 1; off < 32; off <<= 1) {
            int u = __shfl_up_sync(0xFFFFFFFFu, t, off);
            if (lane >= off) t += u;
        }
        wsum[lane] = t;
    }
    __syncthreads();
    int warp_off = (wid == 0) ? 0 : wsum[wid - 1];
    int local_excl = warp_off + incl - c;
    int block_total = wsum[31];

    if (tid == 0) {
        g_part[blockIdx.x] = block_total;
        __threadfence();
        atomicAdd(&g_flag, 1);
        while (atomicAdd(&g_flag, 0) < (int)gridDim.x) { }
        __threadfence();
        int o = 0;
        for (int b = 0; b < (int)blockIdx.x; b++) o += g_part[b];
        s_off = o;
        if (blockIdx.x == gridDim.x - 1) g_rowptr[n] = o + block_total;
    }
    __syncthreads();
    int run = s_off + local_excl;
    if (i < n) {
        g_rowptr[i] = run;
        g_dinv[i]   = rsqrtf((float)c + 1.0f);
    }
}

// atomic-free CSR fill: slot = rowptr[dst] + ordinal
__global__ void fill_k(int E) {
    int e = blockIdx.x * blockDim.x + threadIdx.x;
    if (e >= E) return;
    int d = g_dst[e];
    g_csrc[g_rowptr[d] + g_ord[e]] = g_src[e];
}

// ---------------- HMMA GEMM machinery (64-row tiles, 256 threads) ----------------
__device__ __forceinline__ void stage_A16f(const float* __restrict__ A,
                                           __half* As16, int row_base, int nrows) {
    int tid = threadIdx.x;
    #pragma unroll
    for (int i = tid; i < 64 * 32; i += 256) {
        int r = i >> 5, c4 = i & 31;
        float4 v = make_float4(0.f, 0.f, 0.f, 0.f);
        if (row_base + r < nrows)
            v = ((const float4*)A)[(size_t)(row_base + r) * 32 + c4];
        *(uint2*)(As16 + r * ASTR + c4 * 4) = f4_to_h4(v);
    }
}
__device__ __forceinline__ void stage_A16h(const __half* __restrict__ A,
                                           __half* As16, int row_base, int nrows) {
    int tid = threadIdx.x;
    #pragma unroll
    for (int i = tid; i < 64 * 32; i += 256) {
        int r = i >> 5, c4 = i & 31;
        uint2 v = make_uint2(0u, 0u);
        if (row_base + r < nrows)
            v = ((const uint2*)A)[(size_t)(row_base + r) * 32 + c4];
        *(uint2*)(As16 + r * ASTR + c4 * 4) = v;
    }
}
template<int BN>
__device__ __forceinline__ void stage_W16(const float* __restrict__ W, __half* Ws16) {
    int tid = threadIdx.x;
    #pragma unroll
    for (int i = tid; i < 128 * BN / 4; i += 256) {
        int k = i / (BN / 4), c4 = i % (BN / 4);
        float4 v = ((const float4*)W)[i];
        *(uint2*)(Ws16 + k * ASTR + c4 * 4) = f4_to_h4(v);
    }
}

template<int NT>
__device__ __forceinline__ void hmma_pass(const __half* As16, const __half* Ws16,
                                          int rl0, int nbase, float (&c)[8][4])
{
    const int lane = threadIdx.x & 31;
    const int t = lane >> 3, i = lane & 7;
    #pragma unroll
    for (int k0 = 0; k0 < 128; k0 += 16) {
        unsigned a0, a1, a2, a3;
        {
            int row = rl0 + (t & 1) * 8 + i;
            int col = k0 + (t >> 1) * 8;
            unsigned addr = smem_u32(As16 + row * ASTR + col);
            asm volatile("ldmatrix.sync.aligned.m8n8.x4.shared.b16 {%0,%1,%2,%3}, [%4];"
                : "=r"(a0), "=r"(a1), "=r"(a2), "=r"(a3) : "r"(addr));
        }
        unsigned b[2 * NT];
        #pragma unroll
        for (int m = 0; m < NT / 2; m++) {
            int krow = k0 + (t & 1) * 8 + i;
            int col = nbase + m * 16 + (t >> 1) * 8;
            unsigned addr = smem_u32(Ws16 + krow * ASTR + col);
            asm volatile("ldmatrix.sync.aligned.m8n8.x4.trans.shared.b16 {%0,%1,%2,%3}, [%4];"
                : "=r"(b[4*m]), "=r"(b[4*m+1]), "=r"(b[4*m+2]), "=r"(b[4*m+3]) : "r"(addr));
        }
        #pragma unroll
        for (int j = 0; j < NT; j++)
            hmma16816(c[j][0], c[j][1], c[j][2], c[j][3],
                      a0, a1, a2, a3, b[2*j], b[2*j+1]);
    }
}

// ---------------- GEMM1: g_x16 = fp16(feat @ W_gcn) ----------------
__global__ void __launch_bounds__(256) gemm1_k(
    const float* __restrict__ A, const float* __restrict__ W, int nrows)
{
    extern __shared__ __half sh[];
    __half* As16 = sh;
    __half* Ws16 = sh + 64 * ASTR;
    const int row_base = blockIdx.x * 64;
    const int tid = threadIdx.x, lane = tid & 31, wid = tid >> 5;
    const int rl0 = (wid & 3) * 16;
    const int nbase = (wid >> 2) * 64;

    stage_A16f(A, As16, row_base, nrows);
    stage_W16<128>(W, Ws16);
    __syncthreads();

    float c[8][4];
    #pragma unroll
    for (int j = 0; j < 8; j++)
        #pragma unroll
        for (int q = 0; q < 4; q++) c[j][q] = 0.f;
    hmma_pass<8>(As16, Ws16, rl0, nbase, c);

    int r0 = row_base + rl0 + lane / 4;
    #pragma unroll
    for (int j = 0; j < 8; j++) {
        int cb = nbase + j * 8 + 2 * (lane & 3);
        if (r0 < nrows)
            *(__half2*)&g_x16[(size_t)r0 * 128 + cb] = __floats2half2_rn(c[j][0], c[j][1]);
        if (r0 + 8 < nrows)
            *(__half2*)&g_x16[(size_t)(r0 + 8) * 128 + cb] = __floats2half2_rn(c[j][2], c[j][3]);
    }
}

// ---------------- mega-fused HMMA: SAGE GEMM + value head + 3-layer MLP ----------------
__global__ void __launch_bounds__(256) mlp_fused_k(
    const float* __restrict__ Wl, const float* __restrict__ Wr,
    const float* __restrict__ bl,
    const float* __restrict__ W1, const float* __restrict__ b1,
    const float* __restrict__ W2, const float* __restrict__ b2,
    const float* __restrict__ W3, const float* __restrict__ b3,
    const float* __restrict__ Wv, const float* __restrict__ bv,
    float* __restrict__ means_out, float* __restrict__ values_out, int nrows)
{
    extern __shared__ __half sh[];
    __half* As16 = sh;
    __half* Ws16 = sh + 64 * ASTR;
    const int row_base = blockIdx.x * 64;
    const int tid = threadIdx.x, lane = tid & 31, wid = tid >> 5;
    const int rl0 = (wid & 3) * 16;
    const int nbase = (wid >> 2) * 64;

    float c[8][4];
    #pragma unroll
    for (int j = 0; j < 8; j++)
        #pragma unroll
        for (int q = 0; q < 4; q++) c[j][q] = 0.f;

    // --- SAGE pass 1: ns @ Wl ---
    stage_A16h(g_ns16, As16, row_base, nrows);
    stage_W16<128>(Wl, Ws16);
    __syncthreads();
    hmma_pass<8>(As16, Ws16, rl0, nbase, c);
    __syncthreads();
    // --- SAGE pass 2: + h1 @ Wr ---
    stage_A16h(g_h116, As16, row_base, nrows);
    stage_W16<128>(Wr, Ws16);
    __syncthreads();
    hmma_pass<8>(As16, Ws16, rl0, nbase, c);
    __syncthreads();

    // --- epilogue: h2 = relu(c + bl) -> As16 (fp16) ---
    {
        int rr = rl0 + lane / 4;
        #pragma unroll
        for (int j = 0; j < 8; j++) {
            int cb = nbase + j * 8 + 2 * (lane & 3);
            float v0 = fmaxf(c[j][0] + bl[cb],     0.f);
            float v1 = fmaxf(c[j][1] + bl[cb + 1], 0.f);
            float v2 = fmaxf(c[j][2] + bl[cb],     0.f);
            float v3 = fmaxf(c[j][3] + bl[cb + 1], 0.f);
            *(__half2*)(As16 + rr * ASTR + cb)       = __floats2half2_rn(v0, v1);
            *(__half2*)(As16 + (rr + 8) * ASTR + cb) = __floats2half2_rn(v2, v3);
        }
    }
    __syncthreads();

    // --- value head: values = h2 @ Wv + bv ---
    {
        int row = tid >> 2;          // 0..63
        int sub = tid & 3;           // 0..3
        const __half* hr = As16 + row * ASTR + sub * 32;
        const float* wv = Wv + sub * 32;
        float p = 0.f;
        #pragma unroll
        for (int j = 0; j < 16; j++) {
            __half2 h = *(const __half2*)(hr + 2 * j);
            float2 f = __half22float2(h);
            p = fmaf(f.x, wv[2 * j], p);
            p = fmaf(f.y, wv[2 * j + 1], p);
        }
        p += __shfl_xor_sync(0xFFFFFFFFu, p, 1);
        p += __shfl_xor_sync(0xFFFFFFFFu, p, 2);
        int grow = row_base + row;
        if (sub == 0 && grow < nrows) values_out[grow] = p + bv[0];
    }

    // --- MLP layers 1 & 2: As16 = gelu(As16 @ W + b) ---
    #pragma unroll 1
    for (int layer = 0; layer < 2; layer++) {
        const float* Wp = layer ? W2 : W1;
        const float* bp = layer ? b2 : b1;
        stage_W16<128>(Wp, Ws16);
        __syncthreads();
        #pragma unroll
        for (int j = 0; j < 8; j++)
            #pragma unroll
            for (int q = 0; q < 4; q++) c[j][q] = 0.f;
        hmma_pass<8>(As16, Ws16, rl0, nbase, c);
        __syncthreads();
        int rr = rl0 + lane / 4;
        #pragma unroll
        for (int j = 0; j < 8; j++) {
            int cb = nbase + j * 8 + 2 * (lane & 3);
            float v0 = gelu_f(c[j][0] + bp[cb]);
            float v1 = gelu_f(c[j][1] + bp[cb + 1]);
            float v2 = gelu_f(c[j][2] + bp[cb]);
            float v3 = gelu_f(c[j][3] + bp[cb + 1]);
            *(__half2*)(As16 + rr * ASTR + cb)       = __floats2half2_rn(v0, v1);
            *(__half2*)(As16 + (rr + 8) * ASTR + cb) = __floats2half2_rn(v2, v3);
        }
        __syncthreads();
    }

    // --- MLP layer 3 (BN=64): means = As16 @ W3 + b3 ---
    stage_W16<64>(W3, Ws16);
    __syncthreads();
    {
        const int nb2 = (wid >> 2) * 32;
        #pragma unroll
        for (int j = 0; j < 4; j++)
            #pragma unroll
            for (int q = 0; q < 4; q++) c[j][q] = 0.f;
        hmma_pass<4>(As16, Ws16, rl0, nb2, c);
        int r0 = row_base + rl0 + lane / 4;
        #pragma unroll
        for (int j = 0; j < 4; j++) {
            int cb = nb2 + j * 8 + 2 * (lane & 3);
            float2 o0 = make_float2(c[j][0] + b3[cb], c[j][1] + b3[cb + 1]);
            float2 o1 = make_float2(c[j][2] + b3[cb], c[j][3] + b3[cb + 1]);
            if (r0 < nrows)
                *(float2*)&means_out[(size_t)r0 * 64 + cb] = o0;
            if (r0 + 8 < nrows)
                *(float2*)&means_out[(size_t)(r0 + 8) * 64 + cb] = o1;
        }
    }
}

// ---------------- GCN gather: 2 edges per warp iter (16 lanes x LDG.128) ----
__global__ void gcn_gather_k(const float* __restrict__ bias, int n) {
    int node = blockIdx.x * (blockDim.x >> 5) + (threadIdx.x >> 5);
    if (node >= n) return;
    int lane = threadIdx.x & 31;
    int half = lane >> 4;            // 0 or 1
    int col0 = (lane & 15) * 8;      // 8 halfs per lane
    int beg = g_rowptr[node], end = g_rowptr[node + 1];
    float dd = g_dinv[node];

    float acc[8];
    #pragma unroll
    for (int j = 0; j < 8; j++) acc[j] = 0.f;

    int e = beg + half;
    for (; e + 2 < end; e += 4) {
        int s0 = g_csrc[e], s1 = g_csrc[e + 2];
        uint4 u0 = *(const uint4*)&g_x16[(size_t)s0 * HID + col0];
        uint4 u1 = *(const uint4*)&g_x16[(size_t)s1 * HID + col0];
        float c0 = g_dinv[s0] * dd, c1 = g_dinv[s1] * dd;
        __half2* h0 = (__half2*)&u0;
        __half2* h1 = (__half2*)&u1;
        #pragma unroll
        for (int j = 0; j < 4; j++) {
            float2 f0 = __half22float2(h0[j]);
            float2 f1 = __half22float2(h1[j]);
            acc[2*j]   = fmaf(f0.x, c0, acc[2*j]);
            acc[2*j+1] = fmaf(f0.y, c0, acc[2*j+1]);
            acc[2*j]   = fmaf(f1.x, c1, acc[2*j]);
            acc[2*j+1] = fmaf(f1.y, c1, acc[2*j+1]);
        }
    }
    for (; e < end; e += 2) {
        int s0 = g_csrc[e];
        uint4 u0 = *(const uint4*)&g_x16[(size_t)s0 * HID + col0];
        float c0 = g_dinv[s0] * dd;
        __half2* h0 = (__half2*)&u0;
        #pragma unroll
        for (int j = 0; j < 4; j++) {
            float2 f0 = __half22float2(h0[j]);
            acc[2*j]   = fmaf(f0.x, c0, acc[2*j]);
            acc[2*j+1] = fmaf(f0.y, c0, acc[2*j+1]);
        }
    }
    #pragma unroll
    for (int j = 0; j < 8; j++)
        acc[j] += __shfl_xor_sync(0xFFFFFFFFu, acc[j], 16);

    if (half == 0) {
        uint4 su = *(const uint4*)&g_x16[(size_t)node * HID + col0];
        __half2* sh2 = (__half2*)&su;
        float sl = dd * dd;
        uint4 o;
        __half2* op = (__half2*)&o;
        #pragma unroll
        for (int j = 0; j < 4; j++) {
            float2 sf = __half22float2(sh2[j]);
            float v0 = acc[2*j]   + sf.x * sl + bias[col0 + 2*j];
            float v1 = acc[2*j+1] + sf.y * sl + bias[col0 + 2*j + 1];
            op[j] = __floats2half2_rn(fmaxf(v0, 0.f), fmaxf(v1, 0.f));
        }
        *(uint4*)&g_h116[(size_t)node * HID + col0] = o;
    }
}

// ---------------- SAGE gather: 2 edges per warp iter ----------------
__global__ void sage_gather_k(int n) {
    int node = blockIdx.x * (blockDim.x >> 5) + (threadIdx.x >> 5);
    if (node >= n) return;
    int lane = threadIdx.x & 31;
    int half = lane >> 4;
    int col0 = (lane & 15) * 8;
    int beg = g_rowptr[node], end = g_rowptr[node + 1];

    float acc[8];
    #pragma unroll
    for (int j = 0; j < 8; j++) acc[j] = 0.f;

    int e = beg + half;
    for (; e + 2 < end; e += 4) {
        int s0 = g_csrc[e], s1 = g_csrc[e + 2];
        uint4 u0 = *(const uint4*)&g_h116[(size_t)s0 * HID + col0];
        uint4 u1 = *(const uint4*)&g_h116[(size_t)s1 * HID + col0];
        __half2* h0 = (__half2*)&u0;
        __half2* h1 = (__half2*)&u1;
        #pragma unroll
        for (int j = 0; j < 4; j++) {
            float2 f0 = __half22float2(h0[j]);
            float2 f1 = __half22float2(h1[j]);
            acc[2*j]   += f0.x + f1.x;
            acc[2*j+1] += f0.y + f1.y;
        }
    }
    for (; e < end; e += 2) {
        int s0 = g_csrc[e];
        uint4 u0 = *(const uint4*)&g_h116[(size_t)s0 * HID + col0];
        __half2* h0 = (__half2*)&u0;
        #pragma unroll
        for (int j = 0; j < 4; j++) {
            float2 f0 = __half22float2(h0[j]);
            acc[2*j] += f0.x; acc[2*j+1] += f0.y;
        }
    }
    #pragma unroll
    for (int j = 0; j < 8; j++)
        acc[j] += __shfl_xor_sync(0xFFFFFFFFu, acc[j], 16);

    if (half == 0) {
        int deg = end - beg;
        float inv = 1.0f / (float)max(deg, 1);
        uint4 o;
        __half2* op = (__half2*)&o;
        #pragma unroll
        for (int j = 0; j < 4; j++)
            op[j] = __floats2half2_rn(acc[2*j] * inv, acc[2*j+1] * inv);
        *(uint4*)&g_ns16[(size_t)node * HID + col0] = o;
    }
}

// ---------------- launch ----------------
extern "C" void kernel_launch(void* const* d_in, const int* in_sizes, int n_in,
                              void* d_out, int out_size)
{
    const float* feat     = (const float*)d_in[0];
    const void*  ei       = d_in[1];
    const float* W_gcn    = (const float*)d_in[2];
    const float* b_gcn    = (const float*)d_in[3];
    const float* W_sage_l = (const float*)d_in[4];
    const float* b_sage_l = (const float*)d_in[5];
    const float* W_sage_r = (const float*)d_in[6];
    const float* W1       = (const float*)d_in[7];
    const float* b1       = (const float*)d_in[8];
    const float* W2       = (const float*)d_in[9];
    const float* b2       = (const float*)d_in[10];
    const float* W3       = (const float*)d_in[11];
    const float* b3       = (const float*)d_in[12];
    const float* Wv       = (const float*)d_in[13];
    const float* bv       = (const float*)d_in[14];

    const int N = in_sizes[0] / HID;   // 20000
    const int E = in_sizes[1] / 2;     // 640000

    float* means_out  = (float*)d_out;            // [N, 64]
    float* values_out = (float*)d_out + (size_t)N * 64;

    const int TB = 256;
    const int e_blocks    = (E + TB - 1) / TB;        // 2500
    const int nw_blocks   = (N * 32 + TB - 1) / TB;   // warp per node
    const int scan_blocks = (N + 1023) / 1024;        // 20
    const int gemm_blocks = (N + 63) / 64;            // 313

    const int SMEM = (64 * ASTR + 128 * ASTR) * 2;    // 52224 B

    static int init_done = 0;
    static cudaStream_t s2;
    static cudaEvent_t ev_fork, ev_join;
    if (!init_done) {
        cudaFuncSetAttribute(gemm1_k,
            cudaFuncAttributeMaxDynamicSharedMemorySize, SMEM);
        cudaFuncSetAttribute(mlp_fused_k,
            cudaFuncAttributeMaxDynamicSharedMemorySize, SMEM);
        cudaStreamCreateWithFlags(&s2, cudaStreamNonBlocking);
        cudaEventCreateWithFlags(&ev_fork, cudaEventDisableTiming);
        cudaEventCreateWithFlags(&ev_join, cudaEventDisableTiming);
        init_done = 1;
    }

    // fork: CSR build chain on s2, GEMM1 on main stream — independent
    cudaEventRecord(ev_fork, 0);
    cudaStreamWaitEvent(s2, ev_fork, 0);

    init_k<<<80, TB, 0, s2>>>((const int*)ei, N);
    convert_count_k<<<e_blocks, TB, 0, s2>>>(ei, E);
    scan_fused_k<<<scan_blocks, 1024, 0, s2>>>(N);
    fill_k<<<e_blocks, TB, 0, s2>>>(E);
    cudaEventRecord(ev_join, s2);

    gemm1_k<<<gemm_blocks, TB, SMEM>>>(feat, W_gcn, N);

    // join: gathers need both CSR and g_x16
    cudaStreamWaitEvent(0, ev_join, 0);
    gcn_gather_k<<<nw_blocks, TB>>>(b_gcn, N);
    sage_gather_k<<<nw_blocks, TB>>>(N);
    mlp_fused_k<<<gemm_blocks, TB, SMEM>>>(W_sage_l, W_sage_r, b_sage_l,
                                           W1, b1, W2, b2, W3, b3,
                                           Wv, bv, means_out, values_out, N);
}